// round 12
// baseline (speedup 1.0000x reference)
#include <cuda_runtime.h>
#include <cuda_fp16.h>
#include <cstdint>
#include <math.h>

#define DEVFN static __device__ __forceinline__

// ---------------- problem constants ----------------
constexpr int NN = 12000;
constexpr int FF = 256;
constexpr float SCALE1     = 16384.f;
constexpr float INV_SCALE1 = 1.f / 16384.f;

// ---------------- big-GEMM config (256 thr, BM=128, BN=128, 2 CTA/SM) ----
constexpr int BM = 128;
constexpr int BNH = 128;                           // N per CTA (half of 256)
constexpr int SPLITK = 3;
constexpr int BK = 32;
constexpr int STAGES = 4;
constexpr int PADA = 40;                           // halves per A row (80 B)
constexpr int PADB = 40;                           // halves per B row (80 B)
constexpr int A_BYTES = BM * PADA * 2;             // 10240
constexpr int B_BYTES = BNH * PADB * 2;            // 10240
constexpr int STAGE_BYTES = A_BYTES + B_BYTES;     // 20480
constexpr int DYN_SMEM = STAGES * STAGE_BYTES;     // 81920
constexpr int KCH_BIG = (NN / SPLITK) / BK;        // 125

// ---------------- GEMM2 config (512 thr, BN=256, from R9) ----------------
constexpr int PADA2 = 40;
constexpr int PADB2 = 40;
constexpr int A_BYTES2 = BM * PADA2 * 2;           // 10240
constexpr int B_BYTES2 = 256 * PADB2 * 2;          // 20480
constexpr int STAGE_BYTES2 = A_BYTES2 + B_BYTES2;  // 30720
constexpr int DYN_SMEM2 = STAGES * STAGE_BYTES2;   // 122880

// ---------------- device scratch -------------------
__device__ float g_scores[NN];
__device__ float g_p[NN];
__device__ __half g_scaledT16[(size_t)FF * NN];    // B for GEMM1 (fp16, x2^14)
__device__ __half g_supportT16[(size_t)FF * NN];   // B for GEMM3 (fp16)
__device__ __half g_weightT16[FF * FF];            // B for GEMM2 (fp16)
__device__ float g_part[(size_t)SPLITK * NN * FF]; // split-K partials

// ---------------- PTX helpers ----------------------
DEVFN uint32_t smem_u32(const void* p) {
    uint32_t a;
    asm("{ .reg .u64 t; cvta.to.shared.u64 t, %1; cvt.u32.u64 %0, t; }" : "=r"(a) : "l"(p));
    return a;
}
DEVFN void cp_async16(uint32_t saddr, const void* gaddr) {
    asm volatile("cp.async.cg.shared.global [%0], [%1], 16;"
                 :: "r"(saddr), "l"(gaddr) : "memory");
}
DEVFN void cp_commit() { asm volatile("cp.async.commit_group;" ::: "memory"); }
template <int N> DEVFN void cp_wait() { asm volatile("cp.async.wait_group %0;" :: "n"(N) : "memory"); }

DEVFN void ldmatrix_x4(uint32_t& r0, uint32_t& r1, uint32_t& r2, uint32_t& r3,
                       uint32_t addr) {
    asm volatile("ldmatrix.sync.aligned.m8n8.x4.shared.b16 {%0,%1,%2,%3}, [%4];"
                 : "=r"(r0), "=r"(r1), "=r"(r2), "=r"(r3) : "r"(addr));
}
DEVFN uint32_t pack_h2(float lo, float hi) {
    __half2 h = __float22half2_rn(make_float2(lo, hi));
    return *reinterpret_cast<uint32_t*>(&h);
}
DEVFN void mma_fp16(float* c, const uint32_t* a, const uint32_t* b) {
    asm volatile(
        "mma.sync.aligned.m16n8k16.row.col.f32.f16.f16.f32 "
        "{%0,%1,%2,%3}, {%4,%5,%6,%7}, {%8,%9}, {%0,%1,%2,%3};"
        : "+f"(c[0]), "+f"(c[1]), "+f"(c[2]), "+f"(c[3])
        : "r"(a[0]), "r"(a[1]), "r"(a[2]), "r"(a[3]), "r"(b[0]), "r"(b[1]));
}

// ========================================================================
// Big GEMM partial (256 thr, BN=128, 2 CTA/SM):
//   P[r, n0+c] = fp16(A[r, kSlab]) @ B16[n0+c, kSlab]^T
// blockIdx.x = mtile*2 + nhalf  (N fastest -> paired CTAs share A via L2)
// ========================================================================
__global__ void __launch_bounds__(256, 2)
gemm_h16(const float* __restrict__ A, int lda,
         const __half* __restrict__ B16,
         int M, float* __restrict__ P) {
    extern __shared__ char sm2[];

    const int tid  = threadIdx.x;
    const int wid  = tid >> 5;          // 0..7
    const int lane = tid & 31;
    const int l4   = lane >> 2;
    const int lm   = lane & 3;
    const int m0   = (blockIdx.x >> 1) * BM;
    const int n0   = (blockIdx.x & 1) * BNH;
    const int wm   = (wid >> 1) * 32;   // 0,32,64,96  (4 m-warps)
    const int wn   = (wid & 1) * 64;    // 0,64        (2 n-warps)
    const int kStart = blockIdx.y * KCH_BIG * BK;
    float* __restrict__ Pp = P + (size_t)blockIdx.y * NN * FF;

    const int q = lane >> 3;
    const int rr = lane & 7;
    const uint32_t boff_lane =
        (uint32_t)((wn + (q >> 1) * 8 + rr) * PADB * 2 + (q & 1) * 16);
    const uint32_t aoff_lane =
        (uint32_t)((wm + (lane & 15)) * PADA * 2 + (lane >> 4) * 16);

    // A loader: 128 rows x 2 half-rows of 16 fp32 each
    const int arow = tid >> 1;
    const int aseg = tid & 1;
    const bool arow_ok = (m0 + arow) < M;
    const float* gA = A + (size_t)(m0 + arow) * lda + kStart + aseg * 16;

    float acc[2][8][4];
#pragma unroll
    for (int mt = 0; mt < 2; ++mt)
#pragma unroll
        for (int nt = 0; nt < 8; ++nt)
#pragma unroll
            for (int e = 0; e < 4; ++e) acc[mt][nt][e] = 0.f;

    float4 ra[4];
    auto lda_fetch = [&](int c) {
        if (arow_ok) {
            const float4* g = reinterpret_cast<const float4*>(gA + (size_t)c * BK);
            ra[0] = __ldg(g);
            ra[1] = __ldg(g + 1);
            ra[2] = __ldg(g + 2);
            ra[3] = __ldg(g + 3);
        } else {
            ra[0] = ra[1] = ra[2] = ra[3] = make_float4(0.f, 0.f, 0.f, 0.f);
        }
    };
    auto sts_a = [&](int c) {
        uint4 u0, u1;
        u0.x = pack_h2(ra[0].x, ra[0].y); u0.y = pack_h2(ra[0].z, ra[0].w);
        u0.z = pack_h2(ra[1].x, ra[1].y); u0.w = pack_h2(ra[1].z, ra[1].w);
        u1.x = pack_h2(ra[2].x, ra[2].y); u1.y = pack_h2(ra[2].z, ra[2].w);
        u1.z = pack_h2(ra[3].x, ra[3].y); u1.w = pack_h2(ra[3].z, ra[3].w);
        char* dst = sm2 + (c & (STAGES - 1)) * STAGE_BYTES
                  + (size_t)arow * (PADA * 2) + aseg * 32;
        reinterpret_cast<uint4*>(dst)[0] = u0;
        reinterpret_cast<uint4*>(dst)[1] = u1;
    };
    auto issue_b = [&](int c) {
        const uint32_t dbase =
            smem_u32(sm2 + (c & (STAGES - 1)) * STAGE_BYTES) + A_BYTES;
        const __half* gB = B16 + (size_t)n0 * NN + kStart + (size_t)c * BK;
#pragma unroll
        for (int t = 0; t < 2; ++t) {
            const int idx = tid + t * 256;   // 512 segs: 128 rows x 4
            const int row = idx >> 2, seg = idx & 3;
            cp_async16(dbase + (uint32_t)(row * PADB + seg * 8) * 2,
                       gB + (size_t)row * NN + seg * 8);
        }
        cp_commit();
    };

    lda_fetch(0);
    for (int c = 0; c < STAGES - 1; ++c) issue_b(c);

    for (int c = 0; c < KCH_BIG; ++c) {
        sts_a(c);
        cp_wait<STAGES - 2>();
        __syncthreads();
        if (c + 1 < KCH_BIG) lda_fetch(c + 1);
        if (c + STAGES - 1 < KCH_BIG) issue_b(c + STAGES - 1);
        else cp_commit();

        const char* stage = sm2 + (c & (STAGES - 1)) * STAGE_BYTES;
        const uint32_t bA = smem_u32(stage) + aoff_lane;
        const uint32_t bB = smem_u32(stage + A_BYTES) + boff_lane;

#pragma unroll
        for (int ks = 0; ks < BK; ks += 16) {
            uint32_t af[2][4];
#pragma unroll
            for (int mt = 0; mt < 2; ++mt)
                ldmatrix_x4(af[mt][0], af[mt][1], af[mt][2], af[mt][3],
                            bA + (uint32_t)(mt * 16 * PADA * 2 + ks * 2));
            uint32_t bf[8][2];
#pragma unroll
            for (int i = 0; i < 4; ++i) {
                const uint32_t addr = bB + (uint32_t)(i * 16 * PADB * 2 + ks * 2);
                ldmatrix_x4(bf[2 * i][0], bf[2 * i][1],
                            bf[2 * i + 1][0], bf[2 * i + 1][1], addr);
            }
#pragma unroll
            for (int mt = 0; mt < 2; ++mt)
#pragma unroll
                for (int nt = 0; nt < 8; ++nt)
                    mma_fp16(acc[mt][nt], af[mt], bf[nt]);
        }
    }

#pragma unroll
    for (int mt = 0; mt < 2; ++mt) {
#pragma unroll
        for (int half = 0; half < 2; ++half) {
            const int r = m0 + wm + mt * 16 + l4 + half * 8;
            if (r >= M) continue;
#pragma unroll
            for (int nt = 0; nt < 8; ++nt) {
                const int cb = n0 + wn + nt * 8 + lm * 2;
                float2 v = make_float2(acc[mt][nt][half * 2], acc[mt][nt][half * 2 + 1]);
                *reinterpret_cast<float2*>(&Pp[(size_t)r * FF + cb]) = v;
            }
        }
    }
}

// ========================================================================
// GEMM2 fused (512 thr, BN=256): A = sum(partials)*2^-14 + alpha*input,
//   B = weightT16; epilogue writes supportT16 transposed fp16.
// ========================================================================
__global__ void __launch_bounds__(512, 1)
gemm2_fused(const float* __restrict__ inp,
            const float* __restrict__ alphaPtr,
            const __half* __restrict__ B16,
            int M) {
    extern __shared__ char sm2[];
    constexpr int kChunks = FF / BK;   // 8

    const int tid  = threadIdx.x;
    const int wid  = tid >> 5;
    const int lane = tid & 31;
    const int l4   = lane >> 2;
    const int lm   = lane & 3;
    const int m0   = blockIdx.x * BM;
    const int wm   = (wid >> 2) * 32;
    const int wn   = (wid & 3) * 64;
    const float alpha = __ldg(alphaPtr);

    const int q = lane >> 3;
    const int rr = lane & 7;
    const uint32_t boff_lane =
        (uint32_t)((wn + (q >> 1) * 8 + rr) * PADB2 * 2 + (q & 1) * 16);
    const uint32_t aoff_lane =
        (uint32_t)((wm + (lane & 15)) * PADA2 * 2 + (lane >> 4) * 16);

    const int arow = tid >> 2;
    const int aseg = tid & 3;
    const bool arow_ok = (m0 + arow) < M;
    const size_t abase = (size_t)(m0 + arow) * FF + aseg * 8;

    float acc[2][8][4];
#pragma unroll
    for (int mt = 0; mt < 2; ++mt)
#pragma unroll
        for (int nt = 0; nt < 8; ++nt)
#pragma unroll
            for (int e = 0; e < 4; ++e) acc[mt][nt][e] = 0.f;

    float4 ra0, ra1;
    auto lda_fetch = [&](int c) {
        if (arow_ok) {
            const size_t off = abase + (size_t)c * BK;
            const float4* g0 = reinterpret_cast<const float4*>(&g_part[off]);
            const float4* g1 = reinterpret_cast<const float4*>(&g_part[(size_t)NN * FF + off]);
            const float4* g2 = reinterpret_cast<const float4*>(&g_part[(size_t)2 * NN * FF + off]);
            const float4* gx = reinterpret_cast<const float4*>(&inp[off]);
            float4 p0 = __ldg(g0), p1 = __ldg(g1), p2 = __ldg(g2), x = __ldg(gx);
            ra0.x = (p0.x + p1.x + p2.x) * INV_SCALE1 + alpha * x.x;
            ra0.y = (p0.y + p1.y + p2.y) * INV_SCALE1 + alpha * x.y;
            ra0.z = (p0.z + p1.z + p2.z) * INV_SCALE1 + alpha * x.z;
            ra0.w = (p0.w + p1.w + p2.w) * INV_SCALE1 + alpha * x.w;
            p0 = __ldg(g0 + 1); p1 = __ldg(g1 + 1); p2 = __ldg(g2 + 1); x = __ldg(gx + 1);
            ra1.x = (p0.x + p1.x + p2.x) * INV_SCALE1 + alpha * x.x;
            ra1.y = (p0.y + p1.y + p2.y) * INV_SCALE1 + alpha * x.y;
            ra1.z = (p0.z + p1.z + p2.z) * INV_SCALE1 + alpha * x.z;
            ra1.w = (p0.w + p1.w + p2.w) * INV_SCALE1 + alpha * x.w;
        } else {
            ra0 = make_float4(0.f, 0.f, 0.f, 0.f);
            ra1 = make_float4(0.f, 0.f, 0.f, 0.f);
        }
    };
    auto sts_a = [&](int c) {
        uint4 u;
        u.x = pack_h2(ra0.x, ra0.y);
        u.y = pack_h2(ra0.z, ra0.w);
        u.z = pack_h2(ra1.x, ra1.y);
        u.w = pack_h2(ra1.z, ra1.w);
        char* dst = sm2 + (c & (STAGES - 1)) * STAGE_BYTES2
                  + (size_t)arow * (PADA2 * 2) + aseg * 16;
        *reinterpret_cast<uint4*>(dst) = u;
    };
    auto issue_b = [&](int c) {
        const uint32_t dbase =
            smem_u32(sm2 + (c & (STAGES - 1)) * STAGE_BYTES2) + A_BYTES2;
        const __half* gB = B16 + (size_t)c * BK;
#pragma unroll
        for (int t = 0; t < 2; ++t) {
            const int idx = tid + t * 512;
            const int row = idx >> 2, seg = idx & 3;
            const uint32_t soff = (uint32_t)(row * PADB2 + seg * 8) * 2;
            cp_async16(dbase + soff, gB + (size_t)row * FF + seg * 8);
        }
        cp_commit();
    };

    lda_fetch(0);
    for (int c = 0; c < STAGES - 1; ++c) issue_b(c);

    for (int c = 0; c < kChunks; ++c) {
        sts_a(c);
        cp_wait<STAGES - 2>();
        __syncthreads();
        if (c + 1 < kChunks) lda_fetch(c + 1);
        if (c + STAGES - 1 < kChunks) issue_b(c + STAGES - 1);
        else cp_commit();

        const char* stage = sm2 + (c & (STAGES - 1)) * STAGE_BYTES2;
        const uint32_t bA = smem_u32(stage) + aoff_lane;
        const uint32_t bB = smem_u32(stage + A_BYTES2) + boff_lane;

#pragma unroll
        for (int ks = 0; ks < BK; ks += 16) {
            uint32_t af[2][4];
#pragma unroll
            for (int mt = 0; mt < 2; ++mt)
                ldmatrix_x4(af[mt][0], af[mt][1], af[mt][2], af[mt][3],
                            bA + (uint32_t)(mt * 16 * PADA2 * 2 + ks * 2));
            uint32_t bf[8][2];
#pragma unroll
            for (int i = 0; i < 4; ++i) {
                const uint32_t addr = bB + (uint32_t)(i * 16 * PADB2 * 2 + ks * 2);
                ldmatrix_x4(bf[2 * i][0], bf[2 * i][1],
                            bf[2 * i + 1][0], bf[2 * i + 1][1], addr);
            }
#pragma unroll
            for (int mt = 0; mt < 2; ++mt)
#pragma unroll
                for (int nt = 0; nt < 8; ++nt)
                    mma_fp16(acc[mt][nt], af[mt], bf[nt]);
        }
    }

    // epilogue: supportT16[cb*NN + r] = fp16(acc)
#pragma unroll
    for (int mt = 0; mt < 2; ++mt) {
#pragma unroll
        for (int half = 0; half < 2; ++half) {
            const int r = m0 + wm + mt * 16 + l4 + half * 8;
            if (r >= M) continue;
#pragma unroll
            for (int nt = 0; nt < 8; ++nt) {
                const int cb = wn + nt * 8 + lm * 2;
                g_supportT16[(size_t)cb * NN + r] =
                    __float2half_rn(acc[mt][nt][half * 2]);
                g_supportT16[(size_t)(cb + 1) * NN + r] =
                    __float2half_rn(acc[mt][nt][half * 2 + 1]);
            }
        }
    }
}

// ========================================================================
// reduction / prologue kernels
// ========================================================================
__global__ void reduce_sum_kernel(float* __restrict__ out) {
    const size_t i = ((size_t)blockIdx.x * blockDim.x + threadIdx.x) * 4;
    float4 p0 = *reinterpret_cast<const float4*>(&g_part[i]);
    float4 p1 = *reinterpret_cast<const float4*>(&g_part[(size_t)NN * FF + i]);
    float4 p2 = *reinterpret_cast<const float4*>(&g_part[(size_t)2 * NN * FF + i]);
    float4 r;
    r.x = p0.x + p1.x + p2.x;
    r.y = p0.y + p1.y + p2.y;
    r.z = p0.z + p1.z + p2.z;
    r.w = p0.w + p1.w + p2.w;
    *reinterpret_cast<float4*>(&out[i]) = r;
}

__global__ void scores_kernel(const float* __restrict__ input,
                              const float* __restrict__ attn) {
    const int gw   = (blockIdx.x * blockDim.x + threadIdx.x) >> 5;
    const int lane = threadIdx.x & 31;
    if (gw >= NN) return;
    const float* row = input + (size_t)gw * FF;
    float s = 0.f;
#pragma unroll
    for (int j = 0; j < FF / 32; ++j)
        s += row[lane + 32 * j] * __ldg(&attn[lane + 32 * j]);
#pragma unroll
    for (int o = 16; o; o >>= 1) s += __shfl_xor_sync(0xFFFFFFFFu, s, o);
    if (lane == 0) g_scores[gw] = s;
}

__global__ void softmax_kernel() {
    const int tid = threadIdx.x, lane = tid & 31, warp = tid >> 5;
    __shared__ float red[32];
    __shared__ float s_max, s_sum;
    float m = -3.4e38f;
    for (int i = tid; i < NN; i += 1024) m = fmaxf(m, g_scores[i]);
#pragma unroll
    for (int o = 16; o; o >>= 1) m = fmaxf(m, __shfl_xor_sync(0xFFFFFFFFu, m, o));
    if (lane == 0) red[warp] = m;
    __syncthreads();
    if (warp == 0) {
        m = red[lane];
#pragma unroll
        for (int o = 16; o; o >>= 1) m = fmaxf(m, __shfl_xor_sync(0xFFFFFFFFu, m, o));
        if (lane == 0) s_max = m;
    }
    __syncthreads();
    const float mx = s_max;
    float s = 0.f;
    for (int i = tid; i < NN; i += 1024) s += expf(g_scores[i] - mx);
#pragma unroll
    for (int o = 16; o; o >>= 1) s += __shfl_xor_sync(0xFFFFFFFFu, s, o);
    if (lane == 0) red[warp] = s;
    __syncthreads();
    if (warp == 0) {
        s = red[lane];
#pragma unroll
        for (int o = 16; o; o >>= 1) s += __shfl_xor_sync(0xFFFFFFFFu, s, o);
        if (lane == 0) s_sum = s;
    }
    __syncthreads();
    const float inv = 1.0f / s_sum;
    for (int i = tid; i < NN; i += 1024) g_p[i] = expf(g_scores[i] - mx) * inv;
}

// merged prep: scaledT16 (x<375) + weightT16 (x>=375)
__global__ void prep_kernel(const float* __restrict__ input,
                            const float* __restrict__ weight) {
    __shared__ float t[32][33];
    const int tx = threadIdx.x, ty = threadIdx.y;
    if (blockIdx.x < NN / 32) {
        const int i0 = blockIdx.x * 32, f0 = blockIdx.y * 32;
        t[ty][tx] = g_p[i0 + ty] * SCALE1 * input[(size_t)(i0 + ty) * FF + f0 + tx];
        __syncthreads();
        g_scaledT16[(size_t)(f0 + ty) * NN + i0 + tx] = __float2half_rn(t[tx][ty]);
    } else {
        const int i0 = (blockIdx.x - NN / 32) * 32, o0 = blockIdx.y * 32;
        t[ty][tx] = weight[(size_t)(i0 + ty) * FF + o0 + tx];
        __syncthreads();
        g_weightT16[(size_t)(o0 + ty) * FF + i0 + tx] = __float2half_rn(t[tx][ty]);
    }
}

// ========================================================================
// launch
// ========================================================================
extern "C" void kernel_launch(void* const* d_in, const int* in_sizes, int n_in,
                              void* d_out, int out_size) {
    const float* input  = (const float*)d_in[0];
    const float* adj    = (const float*)d_in[1];
    const float* inc    = (const float*)d_in[2];
    const float* weight = (const float*)d_in[3];
    const float* attn   = (const float*)d_in[4];
    const float* alpha  = (const float*)d_in[5];
    float* out = (float*)d_out;

    cudaFuncSetAttribute(gemm_h16,
                         cudaFuncAttributeMaxDynamicSharedMemorySize, DYN_SMEM);
    cudaFuncSetAttribute(gemm2_fused,
                         cudaFuncAttributeMaxDynamicSharedMemorySize, DYN_SMEM2);

    __half *scaledT16, *supportT16, *weightT16;
    float* part;
    cudaGetSymbolAddress((void**)&scaledT16,  g_scaledT16);
    cudaGetSymbolAddress((void**)&supportT16, g_supportT16);
    cudaGetSymbolAddress((void**)&weightT16,  g_weightT16);
    cudaGetSymbolAddress((void**)&part,       g_part);

    scores_kernel<<<(NN + 7) / 8, 256>>>(input, attn);
    softmax_kernel<<<1, 1024>>>();
    prep_kernel<<<dim3(NN / 32 + FF / 32, FF / 32), dim3(32, 32)>>>(input, weight);

    const int gridM = (NN + BM - 1) / BM;        // 94
    const int redBlocks = (NN * FF / 4) / 1024;  // 750

    // GEMM1 (fp16, B x2^14): partials of adj @ scaled  (188 x 3 CTAs)
    gemm_h16<<<dim3(gridM * 2, SPLITK), 256, DYN_SMEM>>>(adj, NN, scaledT16, NN, part);

    // GEMM2 fused: A = sum(part)*2^-14 + alpha*input; writes supportT16^T
    gemm2_fused<<<gridM, 512, DYN_SMEM2>>>(input, alpha, weightT16, NN);

    // GEMM3 (fp16): partials of incidence @ support
    gemm_h16<<<dim3(gridM * 2, SPLITK), 256, DYN_SMEM>>>(inc, NN, supportT16, NN, part);
    reduce_sum_kernel<<<redBlocks, 1024>>>(out);

    (void)in_sizes; (void)n_in; (void)out_size;
}

// round 13
// speedup vs baseline: 1.1320x; 1.1320x over previous
#include <cuda_runtime.h>
#include <cuda_fp16.h>
#include <cstdint>
#include <math.h>

#define DEVFN static __device__ __forceinline__

// ---------------- problem constants ----------------
constexpr int NN = 12000;
constexpr int FF = 256;
constexpr float SCALE1     = 16384.f;
constexpr float INV_SCALE1 = 1.f / 16384.f;

// ---------------- big-GEMM config (256 thr, BM=64, BN=256, 2 CTA/SM) ----
constexpr int BMG = 64;                            // M per CTA
constexpr int SPLITK = 3;
constexpr int BK = 32;
constexpr int STAGES = 4;
constexpr int PADA = 40;                           // halves per A row (80 B)
constexpr int PADB = 40;                           // halves per B row (80 B)
constexpr int A_BYTES = BMG * PADA * 2;            // 5120
constexpr int B_BYTES = 256 * PADB * 2;            // 20480
constexpr int STAGE_BYTES = A_BYTES + B_BYTES;     // 25600
constexpr int DYN_SMEM = STAGES * STAGE_BYTES;     // 102400
constexpr int KCH_BIG = (NN / SPLITK) / BK;        // 125

// ---------------- GEMM2 config (512 thr, BM=128, BN=256) ----------------
constexpr int BM2 = 128;
constexpr int PADA2 = 40;
constexpr int PADB2 = 40;
constexpr int A_BYTES2 = BM2 * PADA2 * 2;          // 10240
constexpr int B_BYTES2 = 256 * PADB2 * 2;          // 20480
constexpr int STAGE_BYTES2 = A_BYTES2 + B_BYTES2;  // 30720
constexpr int DYN_SMEM2 = STAGES * STAGE_BYTES2;   // 122880

// ---------------- device scratch -------------------
__device__ float g_scores[NN];
__device__ float g_p[NN];
__device__ __half g_scaledT16[(size_t)FF * NN];    // B for GEMM1 (fp16, x2^14)
__device__ __half g_supportT16[(size_t)FF * NN];   // B for GEMM3 (fp16)
__device__ __half g_weightT16[FF * FF];            // B for GEMM2 (fp16)
__device__ float g_part[(size_t)SPLITK * NN * FF]; // split-K partials

// ---------------- PTX helpers ----------------------
DEVFN uint32_t smem_u32(const void* p) {
    uint32_t a;
    asm("{ .reg .u64 t; cvta.to.shared.u64 t, %1; cvt.u32.u64 %0, t; }" : "=r"(a) : "l"(p));
    return a;
}
DEVFN void cp_async16(uint32_t saddr, const void* gaddr) {
    asm volatile("cp.async.cg.shared.global [%0], [%1], 16;"
                 :: "r"(saddr), "l"(gaddr) : "memory");
}
DEVFN void cp_commit() { asm volatile("cp.async.commit_group;" ::: "memory"); }
template <int N> DEVFN void cp_wait() { asm volatile("cp.async.wait_group %0;" :: "n"(N) : "memory"); }

DEVFN void ldmatrix_x4(uint32_t& r0, uint32_t& r1, uint32_t& r2, uint32_t& r3,
                       uint32_t addr) {
    asm volatile("ldmatrix.sync.aligned.m8n8.x4.shared.b16 {%0,%1,%2,%3}, [%4];"
                 : "=r"(r0), "=r"(r1), "=r"(r2), "=r"(r3) : "r"(addr));
}
DEVFN uint32_t pack_h2(float lo, float hi) {
    __half2 h = __float22half2_rn(make_float2(lo, hi));
    return *reinterpret_cast<uint32_t*>(&h);
}
DEVFN void mma_fp16(float* c, const uint32_t* a, const uint32_t* b) {
    asm volatile(
        "mma.sync.aligned.m16n8k16.row.col.f32.f16.f16.f32 "
        "{%0,%1,%2,%3}, {%4,%5,%6,%7}, {%8,%9}, {%0,%1,%2,%3};"
        : "+f"(c[0]), "+f"(c[1]), "+f"(c[2]), "+f"(c[3])
        : "r"(a[0]), "r"(a[1]), "r"(a[2]), "r"(a[3]), "r"(b[0]), "r"(b[1]));
}

// ========================================================================
// Big GEMM partial (256 thr, BM=64, BN=256, 2 CTA/SM):
//   P[r, c] = fp16(A[r, kSlab]) @ B16[c, kSlab]^T
// M-split pairing: co-resident CTAs read DISJOINT A rows (A LDG stays 1x)
// and the SAME B panel (L2-resident fp16).
// ========================================================================
__global__ void __launch_bounds__(256, 2)
gemm_h16(const float* __restrict__ A, int lda,
         const __half* __restrict__ B16,
         int M, float* __restrict__ P) {
    extern __shared__ char sm2[];

    const int tid  = threadIdx.x;
    const int wid  = tid >> 5;          // 0..7
    const int lane = tid & 31;
    const int l4   = lane >> 2;
    const int lm   = lane & 3;
    const int m0   = blockIdx.x * BMG;
    const int wm   = (wid >> 2) * 32;   // 0,32      (2 m-warps)
    const int wn   = (wid & 3) * 64;    // 0..192    (4 n-warps)
    const int kStart = blockIdx.y * KCH_BIG * BK;
    float* __restrict__ Pp = P + (size_t)blockIdx.y * NN * FF;

    const int q = lane >> 3;
    const int rr = lane & 7;
    const uint32_t boff_lane =
        (uint32_t)((wn + (q >> 1) * 8 + rr) * PADB * 2 + (q & 1) * 16);
    const uint32_t aoff_lane =
        (uint32_t)((wm + (lane & 15)) * PADA * 2 + (lane >> 4) * 16);

    // A loader: 64 rows x 4 segs of 8 fp32
    const int arow = tid >> 2;
    const int aseg = tid & 3;
    const bool arow_ok = (m0 + arow) < M;
    const float* gA = A + (size_t)(m0 + arow) * lda + kStart + aseg * 8;

    float acc[2][8][4];
#pragma unroll
    for (int mt = 0; mt < 2; ++mt)
#pragma unroll
        for (int nt = 0; nt < 8; ++nt)
#pragma unroll
            for (int e = 0; e < 4; ++e) acc[mt][nt][e] = 0.f;

    float4 ra0, ra1;
    auto lda_fetch = [&](int c) {
        if (arow_ok) {
            const float4* g = reinterpret_cast<const float4*>(gA + (size_t)c * BK);
            ra0 = __ldg(g);
            ra1 = __ldg(g + 1);
        } else {
            ra0 = make_float4(0.f, 0.f, 0.f, 0.f);
            ra1 = make_float4(0.f, 0.f, 0.f, 0.f);
        }
    };
    auto sts_a = [&](int c) {
        uint4 u;
        u.x = pack_h2(ra0.x, ra0.y);
        u.y = pack_h2(ra0.z, ra0.w);
        u.z = pack_h2(ra1.x, ra1.y);
        u.w = pack_h2(ra1.z, ra1.w);
        char* dst = sm2 + (c & (STAGES - 1)) * STAGE_BYTES
                  + (size_t)arow * (PADA * 2) + aseg * 16;
        *reinterpret_cast<uint4*>(dst) = u;
    };
    auto issue_b = [&](int c) {
        const uint32_t dbase =
            smem_u32(sm2 + (c & (STAGES - 1)) * STAGE_BYTES) + A_BYTES;
        const __half* gB = B16 + kStart + (size_t)c * BK;
#pragma unroll
        for (int t = 0; t < 4; ++t) {
            const int idx = tid + t * 256;   // 1024 segs: 256 rows x 4
            const int row = idx >> 2, seg = idx & 3;
            cp_async16(dbase + (uint32_t)(row * PADB + seg * 8) * 2,
                       gB + (size_t)row * NN + seg * 8);
        }
        cp_commit();
    };

    lda_fetch(0);
    for (int c = 0; c < STAGES - 1; ++c) issue_b(c);

    for (int c = 0; c < KCH_BIG; ++c) {
        sts_a(c);
        cp_wait<STAGES - 2>();
        __syncthreads();
        if (c + 1 < KCH_BIG) lda_fetch(c + 1);
        if (c + STAGES - 1 < KCH_BIG) issue_b(c + STAGES - 1);
        else cp_commit();

        const char* stage = sm2 + (c & (STAGES - 1)) * STAGE_BYTES;
        const uint32_t bA = smem_u32(stage) + aoff_lane;
        const uint32_t bB = smem_u32(stage + A_BYTES) + boff_lane;

#pragma unroll
        for (int ks = 0; ks < BK; ks += 16) {
            uint32_t af[2][4];
#pragma unroll
            for (int mt = 0; mt < 2; ++mt)
                ldmatrix_x4(af[mt][0], af[mt][1], af[mt][2], af[mt][3],
                            bA + (uint32_t)(mt * 16 * PADA * 2 + ks * 2));
            uint32_t bf[8][2];
#pragma unroll
            for (int i = 0; i < 4; ++i) {
                const uint32_t addr = bB + (uint32_t)(i * 16 * PADB * 2 + ks * 2);
                ldmatrix_x4(bf[2 * i][0], bf[2 * i][1],
                            bf[2 * i + 1][0], bf[2 * i + 1][1], addr);
            }
#pragma unroll
            for (int mt = 0; mt < 2; ++mt)
#pragma unroll
                for (int nt = 0; nt < 8; ++nt)
                    mma_fp16(acc[mt][nt], af[mt], bf[nt]);
        }
    }

#pragma unroll
    for (int mt = 0; mt < 2; ++mt) {
#pragma unroll
        for (int half = 0; half < 2; ++half) {
            const int r = m0 + wm + mt * 16 + l4 + half * 8;
            if (r >= M) continue;
#pragma unroll
            for (int nt = 0; nt < 8; ++nt) {
                const int cb = wn + nt * 8 + lm * 2;
                float2 v = make_float2(acc[mt][nt][half * 2], acc[mt][nt][half * 2 + 1]);
                *reinterpret_cast<float2*>(&Pp[(size_t)r * FF + cb]) = v;
            }
        }
    }
}

// ========================================================================
// GEMM2 fused (512 thr, BM=128, BN=256): A = sum(partials)*2^-14 +
//   alpha*input in the loader; epilogue writes supportT16 transposed fp16.
// ========================================================================
__global__ void __launch_bounds__(512, 1)
gemm2_fused(const float* __restrict__ inp,
            const float* __restrict__ alphaPtr,
            const __half* __restrict__ B16,
            int M) {
    extern __shared__ char sm2[];
    constexpr int kChunks = FF / BK;   // 8

    const int tid  = threadIdx.x;
    const int wid  = tid >> 5;
    const int lane = tid & 31;
    const int l4   = lane >> 2;
    const int lm   = lane & 3;
    const int m0   = blockIdx.x * BM2;
    const int wm   = (wid >> 2) * 32;
    const int wn   = (wid & 3) * 64;
    const float alpha = __ldg(alphaPtr);

    const int q = lane >> 3;
    const int rr = lane & 7;
    const uint32_t boff_lane =
        (uint32_t)((wn + (q >> 1) * 8 + rr) * PADB2 * 2 + (q & 1) * 16);
    const uint32_t aoff_lane =
        (uint32_t)((wm + (lane & 15)) * PADA2 * 2 + (lane >> 4) * 16);

    const int arow = tid >> 2;
    const int aseg = tid & 3;
    const bool arow_ok = (m0 + arow) < M;
    const size_t abase = (size_t)(m0 + arow) * FF + aseg * 8;

    float acc[2][8][4];
#pragma unroll
    for (int mt = 0; mt < 2; ++mt)
#pragma unroll
        for (int nt = 0; nt < 8; ++nt)
#pragma unroll
            for (int e = 0; e < 4; ++e) acc[mt][nt][e] = 0.f;

    float4 ra0, ra1;
    auto lda_fetch = [&](int c) {
        if (arow_ok) {
            const size_t off = abase + (size_t)c * BK;
            const float4* g0 = reinterpret_cast<const float4*>(&g_part[off]);
            const float4* g1 = reinterpret_cast<const float4*>(&g_part[(size_t)NN * FF + off]);
            const float4* g2 = reinterpret_cast<const float4*>(&g_part[(size_t)2 * NN * FF + off]);
            const float4* gx = reinterpret_cast<const float4*>(&inp[off]);
            float4 p0 = __ldg(g0), p1 = __ldg(g1), p2 = __ldg(g2), x = __ldg(gx);
            ra0.x = (p0.x + p1.x + p2.x) * INV_SCALE1 + alpha * x.x;
            ra0.y = (p0.y + p1.y + p2.y) * INV_SCALE1 + alpha * x.y;
            ra0.z = (p0.z + p1.z + p2.z) * INV_SCALE1 + alpha * x.z;
            ra0.w = (p0.w + p1.w + p2.w) * INV_SCALE1 + alpha * x.w;
            p0 = __ldg(g0 + 1); p1 = __ldg(g1 + 1); p2 = __ldg(g2 + 1); x = __ldg(gx + 1);
            ra1.x = (p0.x + p1.x + p2.x) * INV_SCALE1 + alpha * x.x;
            ra1.y = (p0.y + p1.y + p2.y) * INV_SCALE1 + alpha * x.y;
            ra1.z = (p0.z + p1.z + p2.z) * INV_SCALE1 + alpha * x.z;
            ra1.w = (p0.w + p1.w + p2.w) * INV_SCALE1 + alpha * x.w;
        } else {
            ra0 = make_float4(0.f, 0.f, 0.f, 0.f);
            ra1 = make_float4(0.f, 0.f, 0.f, 0.f);
        }
    };
    auto sts_a = [&](int c) {
        uint4 u;
        u.x = pack_h2(ra0.x, ra0.y);
        u.y = pack_h2(ra0.z, ra0.w);
        u.z = pack_h2(ra1.x, ra1.y);
        u.w = pack_h2(ra1.z, ra1.w);
        char* dst = sm2 + (c & (STAGES - 1)) * STAGE_BYTES2
                  + (size_t)arow * (PADA2 * 2) + aseg * 16;
        *reinterpret_cast<uint4*>(dst) = u;
    };
    auto issue_b = [&](int c) {
        const uint32_t dbase =
            smem_u32(sm2 + (c & (STAGES - 1)) * STAGE_BYTES2) + A_BYTES2;
        const __half* gB = B16 + (size_t)c * BK;
#pragma unroll
        for (int t = 0; t < 2; ++t) {
            const int idx = tid + t * 512;
            const int row = idx >> 2, seg = idx & 3;
            const uint32_t soff = (uint32_t)(row * PADB2 + seg * 8) * 2;
            cp_async16(dbase + soff, gB + (size_t)row * FF + seg * 8);
        }
        cp_commit();
    };

    lda_fetch(0);
    for (int c = 0; c < STAGES - 1; ++c) issue_b(c);

    for (int c = 0; c < kChunks; ++c) {
        sts_a(c);
        cp_wait<STAGES - 2>();
        __syncthreads();
        if (c + 1 < kChunks) lda_fetch(c + 1);
        if (c + STAGES - 1 < kChunks) issue_b(c + STAGES - 1);
        else cp_commit();

        const char* stage = sm2 + (c & (STAGES - 1)) * STAGE_BYTES2;
        const uint32_t bA = smem_u32(stage) + aoff_lane;
        const uint32_t bB = smem_u32(stage + A_BYTES2) + boff_lane;

#pragma unroll
        for (int ks = 0; ks < BK; ks += 16) {
            uint32_t af[2][4];
#pragma unroll
            for (int mt = 0; mt < 2; ++mt)
                ldmatrix_x4(af[mt][0], af[mt][1], af[mt][2], af[mt][3],
                            bA + (uint32_t)(mt * 16 * PADA2 * 2 + ks * 2));
            uint32_t bf[8][2];
#pragma unroll
            for (int i = 0; i < 4; ++i) {
                const uint32_t addr = bB + (uint32_t)(i * 16 * PADB2 * 2 + ks * 2);
                ldmatrix_x4(bf[2 * i][0], bf[2 * i][1],
                            bf[2 * i + 1][0], bf[2 * i + 1][1], addr);
            }
#pragma unroll
            for (int mt = 0; mt < 2; ++mt)
#pragma unroll
                for (int nt = 0; nt < 8; ++nt)
                    mma_fp16(acc[mt][nt], af[mt], bf[nt]);
        }
    }

    // epilogue: supportT16[cb*NN + r] = fp16(acc)
#pragma unroll
    for (int mt = 0; mt < 2; ++mt) {
#pragma unroll
        for (int half = 0; half < 2; ++half) {
            const int r = m0 + wm + mt * 16 + l4 + half * 8;
            if (r >= M) continue;
#pragma unroll
            for (int nt = 0; nt < 8; ++nt) {
                const int cb = wn + nt * 8 + lm * 2;
                g_supportT16[(size_t)cb * NN + r] =
                    __float2half_rn(acc[mt][nt][half * 2]);
                g_supportT16[(size_t)(cb + 1) * NN + r] =
                    __float2half_rn(acc[mt][nt][half * 2 + 1]);
            }
        }
    }
}

// ========================================================================
// reduction / prologue kernels
// ========================================================================
__global__ void reduce_sum_kernel(float* __restrict__ out) {
    const size_t i = ((size_t)blockIdx.x * blockDim.x + threadIdx.x) * 4;
    float4 p0 = *reinterpret_cast<const float4*>(&g_part[i]);
    float4 p1 = *reinterpret_cast<const float4*>(&g_part[(size_t)NN * FF + i]);
    float4 p2 = *reinterpret_cast<const float4*>(&g_part[(size_t)2 * NN * FF + i]);
    float4 r;
    r.x = p0.x + p1.x + p2.x;
    r.y = p0.y + p1.y + p2.y;
    r.z = p0.z + p1.z + p2.z;
    r.w = p0.w + p1.w + p2.w;
    *reinterpret_cast<float4*>(&out[i]) = r;
}

__global__ void scores_kernel(const float* __restrict__ input,
                              const float* __restrict__ attn) {
    const int gw   = (blockIdx.x * blockDim.x + threadIdx.x) >> 5;
    const int lane = threadIdx.x & 31;
    if (gw >= NN) return;
    const float* row = input + (size_t)gw * FF;
    float s = 0.f;
#pragma unroll
    for (int j = 0; j < FF / 32; ++j)
        s += row[lane + 32 * j] * __ldg(&attn[lane + 32 * j]);
#pragma unroll
    for (int o = 16; o; o >>= 1) s += __shfl_xor_sync(0xFFFFFFFFu, s, o);
    if (lane == 0) g_scores[gw] = s;
}

__global__ void softmax_kernel() {
    const int tid = threadIdx.x, lane = tid & 31, warp = tid >> 5;
    __shared__ float red[32];
    __shared__ float s_max, s_sum;
    float m = -3.4e38f;
    for (int i = tid; i < NN; i += 1024) m = fmaxf(m, g_scores[i]);
#pragma unroll
    for (int o = 16; o; o >>= 1) m = fmaxf(m, __shfl_xor_sync(0xFFFFFFFFu, m, o));
    if (lane == 0) red[warp] = m;
    __syncthreads();
    if (warp == 0) {
        m = red[lane];
#pragma unroll
        for (int o = 16; o; o >>= 1) m = fmaxf(m, __shfl_xor_sync(0xFFFFFFFFu, m, o));
        if (lane == 0) s_max = m;
    }
    __syncthreads();
    const float mx = s_max;
    float s = 0.f;
    for (int i = tid; i < NN; i += 1024) s += expf(g_scores[i] - mx);
#pragma unroll
    for (int o = 16; o; o >>= 1) s += __shfl_xor_sync(0xFFFFFFFFu, s, o);
    if (lane == 0) red[warp] = s;
    __syncthreads();
    if (warp == 0) {
        s = red[lane];
#pragma unroll
        for (int o = 16; o; o >>= 1) s += __shfl_xor_sync(0xFFFFFFFFu, s, o);
        if (lane == 0) s_sum = s;
    }
    __syncthreads();
    const float inv = 1.0f / s_sum;
    for (int i = tid; i < NN; i += 1024) g_p[i] = expf(g_scores[i] - mx) * inv;
}

// merged prep: scaledT16 (x<375) + weightT16 (x>=375)
__global__ void prep_kernel(const float* __restrict__ input,
                            const float* __restrict__ weight) {
    __shared__ float t[32][33];
    const int tx = threadIdx.x, ty = threadIdx.y;
    if (blockIdx.x < NN / 32) {
        const int i0 = blockIdx.x * 32, f0 = blockIdx.y * 32;
        t[ty][tx] = g_p[i0 + ty] * SCALE1 * input[(size_t)(i0 + ty) * FF + f0 + tx];
        __syncthreads();
        g_scaledT16[(size_t)(f0 + ty) * NN + i0 + tx] = __float2half_rn(t[tx][ty]);
    } else {
        const int i0 = (blockIdx.x - NN / 32) * 32, o0 = blockIdx.y * 32;
        t[ty][tx] = weight[(size_t)(i0 + ty) * FF + o0 + tx];
        __syncthreads();
        g_weightT16[(size_t)(o0 + ty) * FF + i0 + tx] = __float2half_rn(t[tx][ty]);
    }
}

// ========================================================================
// launch
// ========================================================================
extern "C" void kernel_launch(void* const* d_in, const int* in_sizes, int n_in,
                              void* d_out, int out_size) {
    const float* input  = (const float*)d_in[0];
    const float* adj    = (const float*)d_in[1];
    const float* inc    = (const float*)d_in[2];
    const float* weight = (const float*)d_in[3];
    const float* attn   = (const float*)d_in[4];
    const float* alpha  = (const float*)d_in[5];
    float* out = (float*)d_out;

    cudaFuncSetAttribute(gemm_h16,
                         cudaFuncAttributeMaxDynamicSharedMemorySize, DYN_SMEM);
    cudaFuncSetAttribute(gemm2_fused,
                         cudaFuncAttributeMaxDynamicSharedMemorySize, DYN_SMEM2);

    __half *scaledT16, *supportT16, *weightT16;
    float* part;
    cudaGetSymbolAddress((void**)&scaledT16,  g_scaledT16);
    cudaGetSymbolAddress((void**)&supportT16, g_supportT16);
    cudaGetSymbolAddress((void**)&weightT16,  g_weightT16);
    cudaGetSymbolAddress((void**)&part,       g_part);

    scores_kernel<<<(NN + 7) / 8, 256>>>(input, attn);
    softmax_kernel<<<1, 1024>>>();
    prep_kernel<<<dim3(NN / 32 + FF / 32, FF / 32), dim3(32, 32)>>>(input, weight);

    const int gridMG = (NN + BMG - 1) / BMG;     // 188
    const int gridM2 = (NN + BM2 - 1) / BM2;     // 94
    const int redBlocks = (NN * FF / 4) / 1024;  // 750

    // GEMM1 (fp16, B x2^14): partials of adj @ scaled  (188 x 3 CTAs)
    gemm_h16<<<dim3(gridMG, SPLITK), 256, DYN_SMEM>>>(adj, NN, scaledT16, NN, part);

    // GEMM2 fused: A = sum(part)*2^-14 + alpha*input; writes supportT16^T
    gemm2_fused<<<gridM2, 512, DYN_SMEM2>>>(input, alpha, weightT16, NN);

    // GEMM3 (fp16): partials of incidence @ support
    gemm_h16<<<dim3(gridMG, SPLITK), 256, DYN_SMEM>>>(inc, NN, supportT16, NN, part);
    reduce_sum_kernel<<<redBlocks, 1024>>>(out);

    (void)in_sizes; (void)n_in; (void)out_size;
}

// round 14
// speedup vs baseline: 1.1977x; 1.0580x over previous
#include <cuda_runtime.h>
#include <cuda_fp16.h>
#include <cstdint>
#include <math.h>

#define DEVFN static __device__ __forceinline__

// ---------------- problem constants ----------------
constexpr int NN = 12000;
constexpr int FF = 256;
constexpr float SCALE1     = 16384.f;
constexpr float INV_SCALE1 = 1.f / 16384.f;

// ---------------- big-GEMM config (R9: 512 thr, BM=128, BN=256) ----------
constexpr int BM = 128;
constexpr int SPLITK = 3;
constexpr int BK = 32;
constexpr int STAGES = 4;
constexpr int PADA = 40;                           // halves per A row (80 B)
constexpr int PADB = 40;                           // halves per B row (80 B)
constexpr int A_BYTES = BM * PADA * 2;             // 10240
constexpr int B_BYTES = 256 * PADB * 2;            // 20480
constexpr int STAGE_BYTES = A_BYTES + B_BYTES;     // 30720
constexpr int DYN_SMEM = STAGES * STAGE_BYTES;     // 122880
constexpr int KCH_BIG = (NN / SPLITK) / BK;        // 125

// ---------------- device scratch -------------------
__device__ float g_scores[NN];
__device__ float g_p[NN];
__device__ __half g_scaledT16[(size_t)FF * NN];    // B for GEMM1 (fp16, x2^14)
__device__ __half g_supportT16[(size_t)FF * NN];   // B for GEMM3 (fp16)
__device__ __half g_weightT16[FF * FF];            // B for GEMM2 (fp16)
__device__ float g_part[(size_t)SPLITK * NN * FF]; // split-K partials

// ---------------- PTX helpers ----------------------
DEVFN uint32_t smem_u32(const void* p) {
    uint32_t a;
    asm("{ .reg .u64 t; cvta.to.shared.u64 t, %1; cvt.u32.u64 %0, t; }" : "=r"(a) : "l"(p));
    return a;
}
DEVFN void cp_async16(uint32_t saddr, const void* gaddr) {
    asm volatile("cp.async.cg.shared.global [%0], [%1], 16;"
                 :: "r"(saddr), "l"(gaddr) : "memory");
}
DEVFN void cp_commit() { asm volatile("cp.async.commit_group;" ::: "memory"); }
template <int N> DEVFN void cp_wait() { asm volatile("cp.async.wait_group %0;" :: "n"(N) : "memory"); }

DEVFN void ldmatrix_x4(uint32_t& r0, uint32_t& r1, uint32_t& r2, uint32_t& r3,
                       uint32_t addr) {
    asm volatile("ldmatrix.sync.aligned.m8n8.x4.shared.b16 {%0,%1,%2,%3}, [%4];"
                 : "=r"(r0), "=r"(r1), "=r"(r2), "=r"(r3) : "r"(addr));
}
DEVFN uint32_t pack_h2(float lo, float hi) {
    __half2 h = __float22half2_rn(make_float2(lo, hi));
    return *reinterpret_cast<uint32_t*>(&h);
}
DEVFN void mma_fp16(float* c, const uint32_t* a, const uint32_t* b) {
    asm volatile(
        "mma.sync.aligned.m16n8k16.row.col.f32.f16.f16.f32 "
        "{%0,%1,%2,%3}, {%4,%5,%6,%7}, {%8,%9}, {%0,%1,%2,%3};"
        : "+f"(c[0]), "+f"(c[1]), "+f"(c[2]), "+f"(c[3])
        : "r"(a[0]), "r"(a[1]), "r"(a[2]), "r"(a[3]), "r"(b[0]), "r"(b[1]));
}

// Interleaved inner-K step: ping-pong B pairs so each ldmatrix overlaps
// the previous pair's 4 MMAs. Peak live fragment regs: af(8) + 2x4 bf.
DEVFN void mma_ks_step(float acc[2][8][4], uint32_t bA, uint32_t bB,
                       int padA, int padB, int ks) {
    uint32_t af[2][4];
#pragma unroll
    for (int mt = 0; mt < 2; ++mt)
        ldmatrix_x4(af[mt][0], af[mt][1], af[mt][2], af[mt][3],
                    bA + (uint32_t)(mt * 16 * padA * 2 + ks * 2));
    uint32_t bq[2][4];
    ldmatrix_x4(bq[0][0], bq[0][1], bq[0][2], bq[0][3],
                bB + (uint32_t)(ks * 2));
#pragma unroll
    for (int i = 0; i < 4; ++i) {
        const int cur = i & 1, nxt = cur ^ 1;
        if (i < 3)
            ldmatrix_x4(bq[nxt][0], bq[nxt][1], bq[nxt][2], bq[nxt][3],
                        bB + (uint32_t)((i + 1) * 16 * padB * 2 + ks * 2));
        mma_fp16(acc[0][2 * i],     af[0], &bq[cur][0]);
        mma_fp16(acc[0][2 * i + 1], af[0], &bq[cur][2]);
        mma_fp16(acc[1][2 * i],     af[1], &bq[cur][0]);
        mma_fp16(acc[1][2 * i + 1], af[1], &bq[cur][2]);
    }
}

// ========================================================================
// Big GEMM partial (R9 shape): P[r,c] = fp16(A[r, kSlab]) @ B16[c, kSlab]^T
// ========================================================================
__global__ void __launch_bounds__(512, 1)
gemm_h16(const float* __restrict__ A, int lda,
         const __half* __restrict__ B16,
         int M, float* __restrict__ P) {
    extern __shared__ char sm2[];

    const int tid  = threadIdx.x;
    const int wid  = tid >> 5;
    const int lane = tid & 31;
    const int l4   = lane >> 2;
    const int lm   = lane & 3;
    const int m0   = blockIdx.x * BM;
    const int wm   = (wid >> 2) * 32;
    const int wn   = (wid & 3) * 64;
    const int kStart = blockIdx.y * KCH_BIG * BK;
    float* __restrict__ Pp = P + (size_t)blockIdx.y * NN * FF;

    const int q = lane >> 3;
    const int rr = lane & 7;
    const uint32_t boff_lane =
        (uint32_t)((wn + (q >> 1) * 8 + rr) * PADB * 2 + (q & 1) * 16);
    const uint32_t aoff_lane =
        (uint32_t)((wm + (lane & 15)) * PADA * 2 + (lane >> 4) * 16);

    const int arow = tid >> 2;
    const int aseg = tid & 3;
    const bool arow_ok = (m0 + arow) < M;
    const float* gA = A + (size_t)(m0 + arow) * lda + kStart + aseg * 8;

    float acc[2][8][4];
#pragma unroll
    for (int mt = 0; mt < 2; ++mt)
#pragma unroll
        for (int nt = 0; nt < 8; ++nt)
#pragma unroll
            for (int e = 0; e < 4; ++e) acc[mt][nt][e] = 0.f;

    float4 ra0, ra1;
    auto lda_fetch = [&](int c) {
        if (arow_ok) {
            const float4* g = reinterpret_cast<const float4*>(gA + (size_t)c * BK);
            ra0 = __ldg(g);
            ra1 = __ldg(g + 1);
        } else {
            ra0 = make_float4(0.f, 0.f, 0.f, 0.f);
            ra1 = make_float4(0.f, 0.f, 0.f, 0.f);
        }
    };
    auto sts_a = [&](int c) {
        uint4 u;
        u.x = pack_h2(ra0.x, ra0.y);
        u.y = pack_h2(ra0.z, ra0.w);
        u.z = pack_h2(ra1.x, ra1.y);
        u.w = pack_h2(ra1.z, ra1.w);
        char* dst = sm2 + (c & (STAGES - 1)) * STAGE_BYTES
                  + (size_t)arow * (PADA * 2) + aseg * 16;
        *reinterpret_cast<uint4*>(dst) = u;
    };
    auto issue_b = [&](int c) {
        const uint32_t dbase =
            smem_u32(sm2 + (c & (STAGES - 1)) * STAGE_BYTES) + A_BYTES;
        const __half* gB = B16 + kStart + (size_t)c * BK;
#pragma unroll
        for (int t = 0; t < 2; ++t) {
            const int idx = tid + t * 512;
            const int row = idx >> 2, seg = idx & 3;
            cp_async16(dbase + (uint32_t)(row * PADB + seg * 8) * 2,
                       gB + (size_t)row * NN + seg * 8);
        }
        cp_commit();
    };

    lda_fetch(0);
    for (int c = 0; c < STAGES - 1; ++c) issue_b(c);

    for (int c = 0; c < KCH_BIG; ++c) {
        sts_a(c);
        cp_wait<STAGES - 2>();
        __syncthreads();
        if (c + 1 < KCH_BIG) lda_fetch(c + 1);
        if (c + STAGES - 1 < KCH_BIG) issue_b(c + STAGES - 1);
        else cp_commit();

        const char* stage = sm2 + (c & (STAGES - 1)) * STAGE_BYTES;
        const uint32_t bA = smem_u32(stage) + aoff_lane;
        const uint32_t bB = smem_u32(stage + A_BYTES) + boff_lane;

#pragma unroll
        for (int ks = 0; ks < BK; ks += 16)
            mma_ks_step(acc, bA, bB, PADA, PADB, ks);
    }

#pragma unroll
    for (int mt = 0; mt < 2; ++mt) {
#pragma unroll
        for (int half = 0; half < 2; ++half) {
            const int r = m0 + wm + mt * 16 + l4 + half * 8;
            if (r >= M) continue;
#pragma unroll
            for (int nt = 0; nt < 8; ++nt) {
                const int cb = wn + nt * 8 + lm * 2;
                float2 v = make_float2(acc[mt][nt][half * 2], acc[mt][nt][half * 2 + 1]);
                *reinterpret_cast<float2*>(&Pp[(size_t)r * FF + cb]) = v;
            }
        }
    }
}

// ========================================================================
// GEMM2 fused: A = sum(partials)*2^-14 + alpha*input (loader computes);
//   B = weightT16; epilogue writes supportT16 transposed fp16.
// ========================================================================
__global__ void __launch_bounds__(512, 1)
gemm2_fused(const float* __restrict__ inp,
            const float* __restrict__ alphaPtr,
            const __half* __restrict__ B16,
            int M) {
    extern __shared__ char sm2[];
    constexpr int kChunks = FF / BK;   // 8

    const int tid  = threadIdx.x;
    const int wid  = tid >> 5;
    const int lane = tid & 31;
    const int l4   = lane >> 2;
    const int lm   = lane & 3;
    const int m0   = blockIdx.x * BM;
    const int wm   = (wid >> 2) * 32;
    const int wn   = (wid & 3) * 64;
    const float alpha = __ldg(alphaPtr);

    const int q = lane >> 3;
    const int rr = lane & 7;
    const uint32_t boff_lane =
        (uint32_t)((wn + (q >> 1) * 8 + rr) * PADB * 2 + (q & 1) * 16);
    const uint32_t aoff_lane =
        (uint32_t)((wm + (lane & 15)) * PADA * 2 + (lane >> 4) * 16);

    const int arow = tid >> 2;
    const int aseg = tid & 3;
    const bool arow_ok = (m0 + arow) < M;
    const size_t abase = (size_t)(m0 + arow) * FF + aseg * 8;

    float acc[2][8][4];
#pragma unroll
    for (int mt = 0; mt < 2; ++mt)
#pragma unroll
        for (int nt = 0; nt < 8; ++nt)
#pragma unroll
            for (int e = 0; e < 4; ++e) acc[mt][nt][e] = 0.f;

    float4 ra0, ra1;
    auto lda_fetch = [&](int c) {
        if (arow_ok) {
            const size_t off = abase + (size_t)c * BK;
            const float4* g0 = reinterpret_cast<const float4*>(&g_part[off]);
            const float4* g1 = reinterpret_cast<const float4*>(&g_part[(size_t)NN * FF + off]);
            const float4* g2 = reinterpret_cast<const float4*>(&g_part[(size_t)2 * NN * FF + off]);
            const float4* gx = reinterpret_cast<const float4*>(&inp[off]);
            float4 p0 = __ldg(g0), p1 = __ldg(g1), p2 = __ldg(g2), x = __ldg(gx);
            ra0.x = (p0.x + p1.x + p2.x) * INV_SCALE1 + alpha * x.x;
            ra0.y = (p0.y + p1.y + p2.y) * INV_SCALE1 + alpha * x.y;
            ra0.z = (p0.z + p1.z + p2.z) * INV_SCALE1 + alpha * x.z;
            ra0.w = (p0.w + p1.w + p2.w) * INV_SCALE1 + alpha * x.w;
            p0 = __ldg(g0 + 1); p1 = __ldg(g1 + 1); p2 = __ldg(g2 + 1); x = __ldg(gx + 1);
            ra1.x = (p0.x + p1.x + p2.x) * INV_SCALE1 + alpha * x.x;
            ra1.y = (p0.y + p1.y + p2.y) * INV_SCALE1 + alpha * x.y;
            ra1.z = (p0.z + p1.z + p2.z) * INV_SCALE1 + alpha * x.z;
            ra1.w = (p0.w + p1.w + p2.w) * INV_SCALE1 + alpha * x.w;
        } else {
            ra0 = make_float4(0.f, 0.f, 0.f, 0.f);
            ra1 = make_float4(0.f, 0.f, 0.f, 0.f);
        }
    };
    auto sts_a = [&](int c) {
        uint4 u;
        u.x = pack_h2(ra0.x, ra0.y);
        u.y = pack_h2(ra0.z, ra0.w);
        u.z = pack_h2(ra1.x, ra1.y);
        u.w = pack_h2(ra1.z, ra1.w);
        char* dst = sm2 + (c & (STAGES - 1)) * STAGE_BYTES
                  + (size_t)arow * (PADA * 2) + aseg * 16;
        *reinterpret_cast<uint4*>(dst) = u;
    };
    auto issue_b = [&](int c) {
        const uint32_t dbase =
            smem_u32(sm2 + (c & (STAGES - 1)) * STAGE_BYTES) + A_BYTES;
        const __half* gB = B16 + (size_t)c * BK;
#pragma unroll
        for (int t = 0; t < 2; ++t) {
            const int idx = tid + t * 512;
            const int row = idx >> 2, seg = idx & 3;
            cp_async16(dbase + (uint32_t)(row * PADB + seg * 8) * 2,
                       gB + (size_t)row * FF + seg * 8);
        }
        cp_commit();
    };

    lda_fetch(0);
    for (int c = 0; c < STAGES - 1; ++c) issue_b(c);

    for (int c = 0; c < kChunks; ++c) {
        sts_a(c);
        cp_wait<STAGES - 2>();
        __syncthreads();
        if (c + 1 < kChunks) lda_fetch(c + 1);
        if (c + STAGES - 1 < kChunks) issue_b(c + STAGES - 1);
        else cp_commit();

        const char* stage = sm2 + (c & (STAGES - 1)) * STAGE_BYTES;
        const uint32_t bA = smem_u32(stage) + aoff_lane;
        const uint32_t bB = smem_u32(stage + A_BYTES) + boff_lane;

#pragma unroll
        for (int ks = 0; ks < BK; ks += 16)
            mma_ks_step(acc, bA, bB, PADA, PADB, ks);
    }

    // epilogue: supportT16[cb*NN + r] = fp16(acc)
#pragma unroll
    for (int mt = 0; mt < 2; ++mt) {
#pragma unroll
        for (int half = 0; half < 2; ++half) {
            const int r = m0 + wm + mt * 16 + l4 + half * 8;
            if (r >= M) continue;
#pragma unroll
            for (int nt = 0; nt < 8; ++nt) {
                const int cb = wn + nt * 8 + lm * 2;
                g_supportT16[(size_t)cb * NN + r] =
                    __float2half_rn(acc[mt][nt][half * 2]);
                g_supportT16[(size_t)(cb + 1) * NN + r] =
                    __float2half_rn(acc[mt][nt][half * 2 + 1]);
            }
        }
    }
}

// ========================================================================
// reduction / prologue kernels
// ========================================================================
__global__ void reduce_sum_kernel(float* __restrict__ out) {
    const size_t i = ((size_t)blockIdx.x * blockDim.x + threadIdx.x) * 4;
    float4 p0 = *reinterpret_cast<const float4*>(&g_part[i]);
    float4 p1 = *reinterpret_cast<const float4*>(&g_part[(size_t)NN * FF + i]);
    float4 p2 = *reinterpret_cast<const float4*>(&g_part[(size_t)2 * NN * FF + i]);
    float4 r;
    r.x = p0.x + p1.x + p2.x;
    r.y = p0.y + p1.y + p2.y;
    r.z = p0.z + p1.z + p2.z;
    r.w = p0.w + p1.w + p2.w;
    *reinterpret_cast<float4*>(&out[i]) = r;
}

__global__ void scores_kernel(const float* __restrict__ input,
                              const float* __restrict__ attn) {
    const int gw   = (blockIdx.x * blockDim.x + threadIdx.x) >> 5;
    const int lane = threadIdx.x & 31;
    if (gw >= NN) return;
    const float* row = input + (size_t)gw * FF;
    float s = 0.f;
#pragma unroll
    for (int j = 0; j < FF / 32; ++j)
        s += row[lane + 32 * j] * __ldg(&attn[lane + 32 * j]);
#pragma unroll
    for (int o = 16; o; o >>= 1) s += __shfl_xor_sync(0xFFFFFFFFu, s, o);
    if (lane == 0) g_scores[gw] = s;
}

__global__ void softmax_kernel() {
    const int tid = threadIdx.x, lane = tid & 31, warp = tid >> 5;
    __shared__ float red[32];
    __shared__ float s_max, s_sum;
    float m = -3.4e38f;
    for (int i = tid; i < NN; i += 1024) m = fmaxf(m, g_scores[i]);
#pragma unroll
    for (int o = 16; o; o >>= 1) m = fmaxf(m, __shfl_xor_sync(0xFFFFFFFFu, m, o));
    if (lane == 0) red[warp] = m;
    __syncthreads();
    if (warp == 0) {
        m = red[lane];
#pragma unroll
        for (int o = 16; o; o >>= 1) m = fmaxf(m, __shfl_xor_sync(0xFFFFFFFFu, m, o));
        if (lane == 0) s_max = m;
    }
    __syncthreads();
    const float mx = s_max;
    float s = 0.f;
    for (int i = tid; i < NN; i += 1024) s += expf(g_scores[i] - mx);
#pragma unroll
    for (int o = 16; o; o >>= 1) s += __shfl_xor_sync(0xFFFFFFFFu, s, o);
    if (lane == 0) red[warp] = s;
    __syncthreads();
    if (warp == 0) {
        s = red[lane];
#pragma unroll
        for (int o = 16; o; o >>= 1) s += __shfl_xor_sync(0xFFFFFFFFu, s, o);
        if (lane == 0) s_sum = s;
    }
    __syncthreads();
    const float inv = 1.0f / s_sum;
    for (int i = tid; i < NN; i += 1024) g_p[i] = expf(g_scores[i] - mx) * inv;
}

// merged prep: scaledT16 (x<375) + weightT16 (x>=375)
__global__ void prep_kernel(const float* __restrict__ input,
                            const float* __restrict__ weight) {
    __shared__ float t[32][33];
    const int tx = threadIdx.x, ty = threadIdx.y;
    if (blockIdx.x < NN / 32) {
        const int i0 = blockIdx.x * 32, f0 = blockIdx.y * 32;
        t[ty][tx] = g_p[i0 + ty] * SCALE1 * input[(size_t)(i0 + ty) * FF + f0 + tx];
        __syncthreads();
        g_scaledT16[(size_t)(f0 + ty) * NN + i0 + tx] = __float2half_rn(t[tx][ty]);
    } else {
        const int i0 = (blockIdx.x - NN / 32) * 32, o0 = blockIdx.y * 32;
        t[ty][tx] = weight[(size_t)(i0 + ty) * FF + o0 + tx];
        __syncthreads();
        g_weightT16[(size_t)(o0 + ty) * FF + i0 + tx] = __float2half_rn(t[tx][ty]);
    }
}

// ========================================================================
// launch
// ========================================================================
extern "C" void kernel_launch(void* const* d_in, const int* in_sizes, int n_in,
                              void* d_out, int out_size) {
    const float* input  = (const float*)d_in[0];
    const float* adj    = (const float*)d_in[1];
    const float* inc    = (const float*)d_in[2];
    const float* weight = (const float*)d_in[3];
    const float* attn   = (const float*)d_in[4];
    const float* alpha  = (const float*)d_in[5];
    float* out = (float*)d_out;

    cudaFuncSetAttribute(gemm_h16,
                         cudaFuncAttributeMaxDynamicSharedMemorySize, DYN_SMEM);
    cudaFuncSetAttribute(gemm2_fused,
                         cudaFuncAttributeMaxDynamicSharedMemorySize, DYN_SMEM);

    __half *scaledT16, *supportT16, *weightT16;
    float* part;
    cudaGetSymbolAddress((void**)&scaledT16,  g_scaledT16);
    cudaGetSymbolAddress((void**)&supportT16, g_supportT16);
    cudaGetSymbolAddress((void**)&weightT16,  g_weightT16);
    cudaGetSymbolAddress((void**)&part,       g_part);

    scores_kernel<<<(NN + 7) / 8, 256>>>(input, attn);
    softmax_kernel<<<1, 1024>>>();
    prep_kernel<<<dim3(NN / 32 + FF / 32, FF / 32), dim3(32, 32)>>>(input, weight);

    const int gridM = (NN + BM - 1) / BM;        // 94
    const int redBlocks = (NN * FF / 4) / 1024;  // 750

    // GEMM1 (fp16, B x2^14): partials of adj @ scaled  (94 x 3 CTAs)
    gemm_h16<<<dim3(gridM, SPLITK), 512, DYN_SMEM>>>(adj, NN, scaledT16, NN, part);

    // GEMM2 fused: A = sum(part)*2^-14 + alpha*input; writes supportT16^T
    gemm2_fused<<<gridM, 512, DYN_SMEM>>>(input, alpha, weightT16, NN);

    // GEMM3 (fp16): partials of incidence @ support
    gemm_h16<<<dim3(gridM, SPLITK), 512, DYN_SMEM>>>(inc, NN, supportT16, NN, part);
    reduce_sum_kernel<<<redBlocks, 1024>>>(out);

    (void)in_sizes; (void)n_in; (void)out_size;
}

// round 15
// speedup vs baseline: 1.2097x; 1.0100x over previous
#include <cuda_runtime.h>
#include <cuda_fp16.h>
#include <cstdint>
#include <math.h>

#define DEVFN static __device__ __forceinline__

// ---------------- problem constants ----------------
constexpr int NN = 12000;
constexpr int FF = 256;
constexpr float SCALE1     = 16384.f;
constexpr float INV_SCALE1 = 1.f / 16384.f;

// ---------------- big-GEMM config (512 thr, BM=128, BN=256) ----------
constexpr int BM = 128;
constexpr int SPLITK = 3;
constexpr int BK = 32;
constexpr int STAGES = 4;
constexpr int PADA = 40;                           // halves per A row (80 B)
constexpr int PADB = 40;                           // halves per B row (80 B)
constexpr int A_BYTES = BM * PADA * 2;             // 10240
constexpr int B_BYTES = 256 * PADB * 2;            // 20480
constexpr int STAGE_BYTES = A_BYTES + B_BYTES;     // 30720
constexpr int DYN_SMEM = STAGES * STAGE_BYTES;     // 122880
constexpr int KCH_BIG = (NN / SPLITK) / BK;        // 125

// ---------------- device scratch -------------------
__device__ float g_scores[NN];
__device__ float g_p[NN];
__device__ __half g_scaledT16[(size_t)FF * NN];    // B for GEMM1 (fp16, x2^14)
__device__ __half g_supportT16[(size_t)FF * NN];   // B for GEMM3 (fp16)
__device__ __half g_weightT16[FF * FF];            // B for GEMM2 (fp16)
__device__ float g_part[(size_t)SPLITK * NN * FF]; // split-K partials

// ---------------- PTX helpers ----------------------
DEVFN uint32_t smem_u32(const void* p) {
    uint32_t a;
    asm("{ .reg .u64 t; cvta.to.shared.u64 t, %1; cvt.u32.u64 %0, t; }" : "=r"(a) : "l"(p));
    return a;
}
DEVFN void cp_async16(uint32_t saddr, const void* gaddr) {
    asm volatile("cp.async.cg.shared.global [%0], [%1], 16;"
                 :: "r"(saddr), "l"(gaddr) : "memory");
}
DEVFN void cp_commit() { asm volatile("cp.async.commit_group;" ::: "memory"); }
template <int N> DEVFN void cp_wait() { asm volatile("cp.async.wait_group %0;" :: "n"(N) : "memory"); }

DEVFN void ldmx4(uint32_t* r, uint32_t addr) {
    asm volatile("ldmatrix.sync.aligned.m8n8.x4.shared.b16 {%0,%1,%2,%3}, [%4];"
                 : "=r"(r[0]), "=r"(r[1]), "=r"(r[2]), "=r"(r[3]) : "r"(addr));
}
DEVFN uint32_t pack_h2(float lo, float hi) {
    __half2 h = __float22half2_rn(make_float2(lo, hi));
    return *reinterpret_cast<uint32_t*>(&h);
}
DEVFN void mma_fp16(float* c, const uint32_t* a, const uint32_t* b) {
    asm volatile(
        "mma.sync.aligned.m16n8k16.row.col.f32.f16.f16.f32 "
        "{%0,%1,%2,%3}, {%4,%5,%6,%7}, {%8,%9}, {%0,%1,%2,%3};"
        : "+f"(c[0]), "+f"(c[1]), "+f"(c[2]), "+f"(c[3])
        : "r"(a[0]), "r"(a[1]), "r"(a[2]), "r"(a[3]), "r"(b[0]), "r"(b[1]));
}

// One nt-pair job: 4 MMAs (2 m-tiles x 2 nt)
DEVFN void mma4(float acc[2][8][4], int pair, const uint32_t af[2][4],
                const uint32_t* bq) {
    mma_fp16(acc[0][2 * pair],     af[0], bq);
    mma_fp16(acc[0][2 * pair + 1], af[0], bq + 2);
    mma_fp16(acc[1][2 * pair],     af[1], bq);
    mma_fp16(acc[1][2 * pair + 1], af[1], bq + 2);
}

// Full-chunk distance-2 pipeline: 8 jobs = 2 ks x 4 nt-pairs.
// Every ldmatrix is issued 2 jobs (8 MMA issues) before first consumption.
// bq ring: slot = job % 3; af double-buffered across the ks boundary.
DEVFN void mma_chunk(float acc[2][8][4], uint32_t bA, uint32_t bB) {
    constexpr uint32_t AP = 16 * PADA * 2;   // 1280: A m-tile pitch
    constexpr uint32_t BP = 16 * PADB * 2;   // 1280: B nt-pair pitch
    uint32_t af[2][2][4];
    uint32_t bq[3][4];
    // prologue: af(ks=0) + jobs 0,1
    ldmx4(af[0][0], bA);
    ldmx4(af[0][1], bA + AP);
    ldmx4(bq[0], bB);
    ldmx4(bq[1], bB + BP);
    // j=0: issue job2
    ldmx4(bq[2], bB + 2 * BP);
    mma4(acc, 0, af[0], bq[0]);
    // j=1: issue job3
    ldmx4(bq[0], bB + 3 * BP);
    mma4(acc, 1, af[0], bq[1]);
    // j=2: issue af(ks=16) + job4 (pair0, ks=16)
    ldmx4(af[1][0], bA + 32);
    ldmx4(af[1][1], bA + AP + 32);
    ldmx4(bq[1], bB + 32);
    mma4(acc, 2, af[0], bq[2]);
    // j=3: issue job5
    ldmx4(bq[2], bB + BP + 32);
    mma4(acc, 3, af[0], bq[0]);
    // j=4: issue job6
    ldmx4(bq[0], bB + 2 * BP + 32);
    mma4(acc, 0, af[1], bq[1]);
    // j=5: issue job7
    ldmx4(bq[1], bB + 3 * BP + 32);
    mma4(acc, 1, af[1], bq[2]);
    // j=6, j=7
    mma4(acc, 2, af[1], bq[0]);
    mma4(acc, 3, af[1], bq[1]);
}

// ========================================================================
// Big GEMM partial: P[r,c] = fp16(A[r, kSlab]) @ B16[c, kSlab]^T
// ========================================================================
__global__ void __launch_bounds__(512, 1)
gemm_h16(const float* __restrict__ A, int lda,
         const __half* __restrict__ B16,
         int M, float* __restrict__ P) {
    extern __shared__ char sm2[];

    const int tid  = threadIdx.x;
    const int wid  = tid >> 5;
    const int lane = tid & 31;
    const int l4   = lane >> 2;
    const int lm   = lane & 3;
    const int m0   = blockIdx.x * BM;
    const int wm   = (wid >> 2) * 32;
    const int wn   = (wid & 3) * 64;
    const int kStart = blockIdx.y * KCH_BIG * BK;
    float* __restrict__ Pp = P + (size_t)blockIdx.y * NN * FF;

    const int q = lane >> 3;
    const int rr = lane & 7;
    const uint32_t boff_lane =
        (uint32_t)((wn + (q >> 1) * 8 + rr) * PADB * 2 + (q & 1) * 16);
    const uint32_t aoff_lane =
        (uint32_t)((wm + (lane & 15)) * PADA * 2 + (lane >> 4) * 16);

    const int arow = tid >> 2;
    const int aseg = tid & 3;
    const bool arow_ok = (m0 + arow) < M;
    const float* gA = A + (size_t)(m0 + arow) * lda + kStart + aseg * 8;

    float acc[2][8][4];
#pragma unroll
    for (int mt = 0; mt < 2; ++mt)
#pragma unroll
        for (int nt = 0; nt < 8; ++nt)
#pragma unroll
            for (int e = 0; e < 4; ++e) acc[mt][nt][e] = 0.f;

    float4 ra0, ra1;
    auto lda_fetch = [&](int c) {
        if (arow_ok) {
            const float4* g = reinterpret_cast<const float4*>(gA + (size_t)c * BK);
            ra0 = __ldg(g);
            ra1 = __ldg(g + 1);
        } else {
            ra0 = make_float4(0.f, 0.f, 0.f, 0.f);
            ra1 = make_float4(0.f, 0.f, 0.f, 0.f);
        }
    };
    auto sts_a = [&](int c) {
        uint4 u;
        u.x = pack_h2(ra0.x, ra0.y);
        u.y = pack_h2(ra0.z, ra0.w);
        u.z = pack_h2(ra1.x, ra1.y);
        u.w = pack_h2(ra1.z, ra1.w);
        char* dst = sm2 + (c & (STAGES - 1)) * STAGE_BYTES
                  + (size_t)arow * (PADA * 2) + aseg * 16;
        *reinterpret_cast<uint4*>(dst) = u;
    };
    auto issue_b = [&](int c) {
        const uint32_t dbase =
            smem_u32(sm2 + (c & (STAGES - 1)) * STAGE_BYTES) + A_BYTES;
        const __half* gB = B16 + kStart + (size_t)c * BK;
#pragma unroll
        for (int t = 0; t < 2; ++t) {
            const int idx = tid + t * 512;
            const int row = idx >> 2, seg = idx & 3;
            cp_async16(dbase + (uint32_t)(row * PADB + seg * 8) * 2,
                       gB + (size_t)row * NN + seg * 8);
        }
        cp_commit();
    };

    lda_fetch(0);
    for (int c = 0; c < STAGES - 1; ++c) issue_b(c);

    for (int c = 0; c < KCH_BIG; ++c) {
        sts_a(c);
        cp_wait<STAGES - 2>();
        __syncthreads();
        if (c + 1 < KCH_BIG) lda_fetch(c + 1);
        if (c + STAGES - 1 < KCH_BIG) issue_b(c + STAGES - 1);
        else cp_commit();

        const char* stage = sm2 + (c & (STAGES - 1)) * STAGE_BYTES;
        mma_chunk(acc, smem_u32(stage) + aoff_lane,
                  smem_u32(stage + A_BYTES) + boff_lane);
    }

#pragma unroll
    for (int mt = 0; mt < 2; ++mt) {
#pragma unroll
        for (int half = 0; half < 2; ++half) {
            const int r = m0 + wm + mt * 16 + l4 + half * 8;
            if (r >= M) continue;
#pragma unroll
            for (int nt = 0; nt < 8; ++nt) {
                const int cb = wn + nt * 8 + lm * 2;
                float2 v = make_float2(acc[mt][nt][half * 2], acc[mt][nt][half * 2 + 1]);
                *reinterpret_cast<float2*>(&Pp[(size_t)r * FF + cb]) = v;
            }
        }
    }
}

// ========================================================================
// GEMM2 fused: A = sum(partials)*2^-14 + alpha*input (loader computes);
//   B = weightT16; epilogue writes supportT16 transposed fp16.
// ========================================================================
__global__ void __launch_bounds__(512, 1)
gemm2_fused(const float* __restrict__ inp,
            const float* __restrict__ alphaPtr,
            const __half* __restrict__ B16,
            int M) {
    extern __shared__ char sm2[];
    constexpr int kChunks = FF / BK;   // 8

    const int tid  = threadIdx.x;
    const int wid  = tid >> 5;
    const int lane = tid & 31;
    const int l4   = lane >> 2;
    const int lm   = lane & 3;
    const int m0   = blockIdx.x * BM;
    const int wm   = (wid >> 2) * 32;
    const int wn   = (wid & 3) * 64;
    const float alpha = __ldg(alphaPtr);

    const int q = lane >> 3;
    const int rr = lane & 7;
    const uint32_t boff_lane =
        (uint32_t)((wn + (q >> 1) * 8 + rr) * PADB * 2 + (q & 1) * 16);
    const uint32_t aoff_lane =
        (uint32_t)((wm + (lane & 15)) * PADA * 2 + (lane >> 4) * 16);

    const int arow = tid >> 2;
    const int aseg = tid & 3;
    const bool arow_ok = (m0 + arow) < M;
    const size_t abase = (size_t)(m0 + arow) * FF + aseg * 8;

    float acc[2][8][4];
#pragma unroll
    for (int mt = 0; mt < 2; ++mt)
#pragma unroll
        for (int nt = 0; nt < 8; ++nt)
#pragma unroll
            for (int e = 0; e < 4; ++e) acc[mt][nt][e] = 0.f;

    float4 ra0, ra1;
    auto lda_fetch = [&](int c) {
        if (arow_ok) {
            const size_t off = abase + (size_t)c * BK;
            const float4* g0 = reinterpret_cast<const float4*>(&g_part[off]);
            const float4* g1 = reinterpret_cast<const float4*>(&g_part[(size_t)NN * FF + off]);
            const float4* g2 = reinterpret_cast<const float4*>(&g_part[(size_t)2 * NN * FF + off]);
            const float4* gx = reinterpret_cast<const float4*>(&inp[off]);
            float4 p0 = __ldg(g0), p1 = __ldg(g1), p2 = __ldg(g2), x = __ldg(gx);
            ra0.x = (p0.x + p1.x + p2.x) * INV_SCALE1 + alpha * x.x;
            ra0.y = (p0.y + p1.y + p2.y) * INV_SCALE1 + alpha * x.y;
            ra0.z = (p0.z + p1.z + p2.z) * INV_SCALE1 + alpha * x.z;
            ra0.w = (p0.w + p1.w + p2.w) * INV_SCALE1 + alpha * x.w;
            p0 = __ldg(g0 + 1); p1 = __ldg(g1 + 1); p2 = __ldg(g2 + 1); x = __ldg(gx + 1);
            ra1.x = (p0.x + p1.x + p2.x) * INV_SCALE1 + alpha * x.x;
            ra1.y = (p0.y + p1.y + p2.y) * INV_SCALE1 + alpha * x.y;
            ra1.z = (p0.z + p1.z + p2.z) * INV_SCALE1 + alpha * x.z;
            ra1.w = (p0.w + p1.w + p2.w) * INV_SCALE1 + alpha * x.w;
        } else {
            ra0 = make_float4(0.f, 0.f, 0.f, 0.f);
            ra1 = make_float4(0.f, 0.f, 0.f, 0.f);
        }
    };
    auto sts_a = [&](int c) {
        uint4 u;
        u.x = pack_h2(ra0.x, ra0.y);
        u.y = pack_h2(ra0.z, ra0.w);
        u.z = pack_h2(ra1.x, ra1.y);
        u.w = pack_h2(ra1.z, ra1.w);
        char* dst = sm2 + (c & (STAGES - 1)) * STAGE_BYTES
                  + (size_t)arow * (PADA * 2) + aseg * 16;
        *reinterpret_cast<uint4*>(dst) = u;
    };
    auto issue_b = [&](int c) {
        const uint32_t dbase =
            smem_u32(sm2 + (c & (STAGES - 1)) * STAGE_BYTES) + A_BYTES;
        const __half* gB = B16 + (size_t)c * BK;
#pragma unroll
        for (int t = 0; t < 2; ++t) {
            const int idx = tid + t * 512;
            const int row = idx >> 2, seg = idx & 3;
            cp_async16(dbase + (uint32_t)(row * PADB + seg * 8) * 2,
                       gB + (size_t)row * FF + seg * 8);
        }
        cp_commit();
    };

    lda_fetch(0);
    for (int c = 0; c < STAGES - 1; ++c) issue_b(c);

    for (int c = 0; c < kChunks; ++c) {
        sts_a(c);
        cp_wait<STAGES - 2>();
        __syncthreads();
        if (c + 1 < kChunks) lda_fetch(c + 1);
        if (c + STAGES - 1 < kChunks) issue_b(c + STAGES - 1);
        else cp_commit();

        const char* stage = sm2 + (c & (STAGES - 1)) * STAGE_BYTES;
        mma_chunk(acc, smem_u32(stage) + aoff_lane,
                  smem_u32(stage + A_BYTES) + boff_lane);
    }

    // epilogue: supportT16[cb*NN + r] = fp16(acc)
#pragma unroll
    for (int mt = 0; mt < 2; ++mt) {
#pragma unroll
        for (int half = 0; half < 2; ++half) {
            const int r = m0 + wm + mt * 16 + l4 + half * 8;
            if (r >= M) continue;
#pragma unroll
            for (int nt = 0; nt < 8; ++nt) {
                const int cb = wn + nt * 8 + lm * 2;
                g_supportT16[(size_t)cb * NN + r] =
                    __float2half_rn(acc[mt][nt][half * 2]);
                g_supportT16[(size_t)(cb + 1) * NN + r] =
                    __float2half_rn(acc[mt][nt][half * 2 + 1]);
            }
        }
    }
}

// ========================================================================
// reduction / prologue kernels
// ========================================================================
__global__ void reduce_sum_kernel(float* __restrict__ out) {
    const size_t i = ((size_t)blockIdx.x * blockDim.x + threadIdx.x) * 4;
    float4 p0 = *reinterpret_cast<const float4*>(&g_part[i]);
    float4 p1 = *reinterpret_cast<const float4*>(&g_part[(size_t)NN * FF + i]);
    float4 p2 = *reinterpret_cast<const float4*>(&g_part[(size_t)2 * NN * FF + i]);
    float4 r;
    r.x = p0.x + p1.x + p2.x;
    r.y = p0.y + p1.y + p2.y;
    r.z = p0.z + p1.z + p2.z;
    r.w = p0.w + p1.w + p2.w;
    *reinterpret_cast<float4*>(&out[i]) = r;
}

__global__ void scores_kernel(const float* __restrict__ input,
                              const float* __restrict__ attn) {
    const int gw   = (blockIdx.x * blockDim.x + threadIdx.x) >> 5;
    const int lane = threadIdx.x & 31;
    if (gw >= NN) return;
    const float* row = input + (size_t)gw * FF;
    float s = 0.f;
#pragma unroll
    for (int j = 0; j < FF / 32; ++j)
        s += row[lane + 32 * j] * __ldg(&attn[lane + 32 * j]);
#pragma unroll
    for (int o = 16; o; o >>= 1) s += __shfl_xor_sync(0xFFFFFFFFu, s, o);
    if (lane == 0) g_scores[gw] = s;
}

__global__ void softmax_kernel() {
    const int tid = threadIdx.x, lane = tid & 31, warp = tid >> 5;
    __shared__ float red[32];
    __shared__ float s_max, s_sum;
    float m = -3.4e38f;
    for (int i = tid; i < NN; i += 1024) m = fmaxf(m, g_scores[i]);
#pragma unroll
    for (int o = 16; o; o >>= 1) m = fmaxf(m, __shfl_xor_sync(0xFFFFFFFFu, m, o));
    if (lane == 0) red[warp] = m;
    __syncthreads();
    if (warp == 0) {
        m = red[lane];
#pragma unroll
        for (int o = 16; o; o >>= 1) m = fmaxf(m, __shfl_xor_sync(0xFFFFFFFFu, m, o));
        if (lane == 0) s_max = m;
    }
    __syncthreads();
    const float mx = s_max;
    float s = 0.f;
    for (int i = tid; i < NN; i += 1024) s += expf(g_scores[i] - mx);
#pragma unroll
    for (int o = 16; o; o >>= 1) s += __shfl_xor_sync(0xFFFFFFFFu, s, o);
    if (lane == 0) red[warp] = s;
    __syncthreads();
    if (warp == 0) {
        s = red[lane];
#pragma unroll
        for (int o = 16; o; o >>= 1) s += __shfl_xor_sync(0xFFFFFFFFu, s, o);
        if (lane == 0) s_sum = s;
    }
    __syncthreads();
    const float inv = 1.0f / s_sum;
    for (int i = tid; i < NN; i += 1024) g_p[i] = expf(g_scores[i] - mx) * inv;
}

// merged prep: scaledT16 (x<375) + weightT16 (x>=375)
__global__ void prep_kernel(const float* __restrict__ input,
                            const float* __restrict__ weight) {
    __shared__ float t[32][33];
    const int tx = threadIdx.x, ty = threadIdx.y;
    if (blockIdx.x < NN / 32) {
        const int i0 = blockIdx.x * 32, f0 = blockIdx.y * 32;
        t[ty][tx] = g_p[i0 + ty] * SCALE1 * input[(size_t)(i0 + ty) * FF + f0 + tx];
        __syncthreads();
        g_scaledT16[(size_t)(f0 + ty) * NN + i0 + tx] = __float2half_rn(t[tx][ty]);
    } else {
        const int i0 = (blockIdx.x - NN / 32) * 32, o0 = blockIdx.y * 32;
        t[ty][tx] = weight[(size_t)(i0 + ty) * FF + o0 + tx];
        __syncthreads();
        g_weightT16[(size_t)(o0 + ty) * FF + i0 + tx] = __float2half_rn(t[tx][ty]);
    }
}

// ========================================================================
// launch
// ========================================================================
extern "C" void kernel_launch(void* const* d_in, const int* in_sizes, int n_in,
                              void* d_out, int out_size) {
    const float* input  = (const float*)d_in[0];
    const float* adj    = (const float*)d_in[1];
    const float* inc    = (const float*)d_in[2];
    const float* weight = (const float*)d_in[3];
    const float* attn   = (const float*)d_in[4];
    const float* alpha  = (const float*)d_in[5];
    float* out = (float*)d_out;

    cudaFuncSetAttribute(gemm_h16,
                         cudaFuncAttributeMaxDynamicSharedMemorySize, DYN_SMEM);
    cudaFuncSetAttribute(gemm2_fused,
                         cudaFuncAttributeMaxDynamicSharedMemorySize, DYN_SMEM);

    __half *scaledT16, *supportT16, *weightT16;
    float* part;
    cudaGetSymbolAddress((void**)&scaledT16,  g_scaledT16);
    cudaGetSymbolAddress((void**)&supportT16, g_supportT16);
    cudaGetSymbolAddress((void**)&weightT16,  g_weightT16);
    cudaGetSymbolAddress((void**)&part,       g_part);

    scores_kernel<<<(NN + 7) / 8, 256>>>(input, attn);
    softmax_kernel<<<1, 1024>>>();
    prep_kernel<<<dim3(NN / 32 + FF / 32, FF / 32), dim3(32, 32)>>>(input, weight);

    const int gridM = (NN + BM - 1) / BM;        // 94
    const int redBlocks = (NN * FF / 4) / 1024;  // 750

    // GEMM1 (fp16, B x2^14): partials of adj @ scaled
    gemm_h16<<<dim3(gridM, SPLITK), 512, DYN_SMEM>>>(adj, NN, scaledT16, NN, part);

    // GEMM2 fused: A = sum(part)*2^-14 + alpha*input; writes supportT16^T
    gemm2_fused<<<gridM, 512, DYN_SMEM>>>(input, alpha, weightT16, NN);

    // GEMM3 (fp16): partials of incidence @ support
    gemm_h16<<<dim3(gridM, SPLITK), 512, DYN_SMEM>>>(inc, NN, supportT16, NN, part);
    reduce_sum_kernel<<<redBlocks, 1024>>>(out);

    (void)in_sizes; (void)n_in; (void)out_size;
}